// round 17
// baseline (speedup 1.0000x reference)
#include <cuda_runtime.h>
#include <cuda_bf16.h>
#include <mma.h>
#include <cstdint>

using namespace nvcuda;

#define D_BINS 59
#define C_CH   80
#define O_TOT  139
#define B_     4
#define N_     6
#define CIN    256
#define H_     16
#define W_     44
#define HW     704              // H_*W_
#define NPIX   (B_*N_*H_*W_)    // 16896 = 264 * 64
#define NCELL  (B_*128*128)     // 65536
#define BEVW   128
#define CAP    64               // Poisson(15.2), P(>=64)~1e-28/cell — safe
#define STAGE  32
#define GCELLS 32
#define NOUT   144              // padded N
#define KC     32               // K-chunk
#define ASTR   40               // smem stride (bf16), 80B = 16B-multiple
#define BSTR   40
#define DSTR   61               // s_dep row stride

// ---- device scratch (no allocations; zero-initialized at load) ----
__device__ float g_ctx[NPIX*C_CH];         // [pix][c] fp32 ctx, 5.4 MB (L2-resident)
__device__ int   g_cnt[NCELL];             // per-cell counts (reset by gather)
__device__ int2  g_bin[NCELL*CAP];         // {pix, depth-bits}, 33.5 MB

// ============================================================================
// K1: wmma bf16-split GEMM + FUSED softmax(59) + cell binning.
// (FROZEN at R16 measured-best: 2 CTAs/SM, 64px x 144o, warp tile 16x48.)
// ============================================================================
__global__ __launch_bounds__(384, 2) void gemm_fused_kernel(
    const float* __restrict__ img, const float* __restrict__ wd,
    const float* __restrict__ bd,  const int*   __restrict__ geom)
{
    __shared__ __align__(16) char smem_buf[33280];
    __nv_bfloat16* sAh = (__nv_bfloat16*)smem_buf;            // 5120
    __nv_bfloat16* sAl = sAh + 64 * ASTR;                     // +5120 = 10240
    __nv_bfloat16* sBh = (__nv_bfloat16*)(smem_buf + 10240);  // 11520
    __nv_bfloat16* sBl = sBh + NOUT * BSTR;                   // +11520 = 33280
    float* scr  = (float*)smem_buf;                           // 15360
    float* sdep = (float*)(smem_buf + 15360);                 // 64*61*4 = 15616

    const int tid  = threadIdx.x;
    const int warp = tid >> 5;
    const int lane = tid & 31;
    const int wm   = warp & 3;        // 0..3  (M, 16 px each)
    const int wn   = warp >> 2;       // 0..2  (N, 48 o each)
    const int px0  = blockIdx.x * 64;

    wmma::fragment<wmma::accumulator, 16, 16, 16, float> cf[3];
#pragma unroll
    for (int nt = 0; nt < 3; nt++) wmma::fill_fragment(cf[nt], 0.f);

    for (int ck = 0; ck < 8; ck++) {
        __syncthreads();
#pragma unroll
        for (int r = 0; r < 6; r++) {
            int i = tid + 384 * r;
            if (i < 64 * KC) {
                int c    = i >> 6;
                int px_l = i & 63;
                int px = px0 + px_l;
                int bn = px / HW;
                int hw = px - bn * HW;
                float x = __ldg(&img[(size_t)bn * CIN * HW + (ck * KC + c) * HW + hw]);
                __nv_bfloat16 h = __float2bfloat16(x);
                __nv_bfloat16 l = __float2bfloat16(x - __bfloat162float(h));
                sAh[px_l * ASTR + c] = h;
                sAl[px_l * ASTR + c] = l;
            }
        }
#pragma unroll
        for (int r = 0; r < 12; r++) {
            int i = tid + 384 * r;
            if (i < NOUT * KC) {
                int n = i >> 5;
                int c = i & 31;
                float w = (n < O_TOT) ? __ldg(&wd[n * CIN + ck * KC + c]) : 0.f;
                __nv_bfloat16 h = __float2bfloat16(w);
                __nv_bfloat16 l = __float2bfloat16(w - __bfloat162float(h));
                sBh[n * BSTR + c] = h;
                sBl[n * BSTR + c] = l;
            }
        }
        __syncthreads();

#pragma unroll
        for (int ks = 0; ks < 2; ks++) {
            wmma::fragment<wmma::matrix_a, 16, 16, 16, __nv_bfloat16, wmma::row_major> ah, al;
            const int arow = wm * 16;
            wmma::load_matrix_sync(ah, &sAh[arow * ASTR + ks * 16], ASTR);
            wmma::load_matrix_sync(al, &sAl[arow * ASTR + ks * 16], ASTR);
#pragma unroll
            for (int nt = 0; nt < 3; nt++) {
                const int brow = wn * 48 + nt * 16;
                wmma::fragment<wmma::matrix_b, 16, 16, 16, __nv_bfloat16, wmma::col_major> bh, bl;
                wmma::load_matrix_sync(bh, &sBh[brow * BSTR + ks * 16], BSTR);
                wmma::load_matrix_sync(bl, &sBl[brow * BSTR + ks * 16], BSTR);
                wmma::mma_sync(cf[nt], ah, bh, cf[nt]);
                wmma::mma_sync(cf[nt], ah, bl, cf[nt]);
                wmma::mma_sync(cf[nt], al, bh, cf[nt]);
            }
        }
    }

    __syncthreads();
    float* wscr = scr + warp * 320;
#pragma unroll
    for (int nt = 0; nt < 3; nt++) {
        wmma::store_matrix_sync(wscr, cf[nt], 20, wmma::mem_row_major);
        __syncwarp();
#pragma unroll
        for (int e = 0; e < 8; e++) {
            int idx = lane + e * 32;
            int r   = idx >> 4;
            int col = idx & 15;
            int o = wn * 48 + nt * 16 + col;
            int p_l = wm * 16 + r;
            if (o < O_TOT) {
                float v = wscr[r * 20 + col] + __ldg(&bd[o]);
                if (o < D_BINS) sdep[p_l * DSTR + o] = v;
                else            g_ctx[(px0 + p_l) * C_CH + (o - D_BINS)] = v;
            }
        }
        __syncwarp();
    }
    __syncthreads();

    for (int px_l = warp; px_l < 64; px_l += 12) {
        float* dp = &sdep[px_l * DSTR];
        float v0 = (lane < D_BINS)        ? dp[lane]      : -1e30f;
        float v1 = ((lane + 32) < D_BINS) ? dp[lane + 32] : -1e30f;
        float m = fmaxf(v0, v1);
#pragma unroll
        for (int off = 16; off; off >>= 1)
            m = fmaxf(m, __shfl_xor_sync(0xffffffffu, m, off));
        float e0 = (lane < D_BINS)        ? expf(v0 - m) : 0.f;
        float e1 = ((lane + 32) < D_BINS) ? expf(v1 - m) : 0.f;
        float s = e0 + e1;
#pragma unroll
        for (int off = 16; off; off >>= 1)
            s += __shfl_xor_sync(0xffffffffu, s, off);
        float inv = 1.0f / s;
        if (lane < D_BINS)        dp[lane]      = e0 * inv;
        if ((lane + 32) < D_BINS) dp[lane + 32] = e1 * inv;
    }
    __syncthreads();

    {
        const int2* g2 = (const int2*)geom;
        for (int i = tid; i < D_BINS * 64; i += 384) {
            int d    = i >> 6;
            int px_l = i & 63;
            int px = px0 + px_l;
            int bn = px / HW;
            int hw = px - bn * HW;
            int b  = bn / N_;
            int2 g = __ldg(&g2[(bn * D_BINS + d) * HW + hw]);
            int cell = (b << 14) + g.x * BEVW + g.y;
            int slot = atomicAdd(&g_cnt[cell], 1);
            if (slot < CAP)
                g_bin[cell * CAP + slot] =
                    make_int2(px, __float_as_int(sdep[px_l * DSTR + d]));
        }
    }
}

// ============================================================================
// K3: GATHER v5. 2048 blocks x 128 threads; block = 32 cells, warp = 8 cells
// in TWO QUADS. Each quad: 4 independent accumulation chains, chunk-of-2 per
// cell -> 8 LDG.128 in flight, per-cell startup bubbles amortized 4-ways.
// Warp-UNIFORM skip guards (cs[q] is uniform) stop short cells early —
// no wasted LDS/LDG/FMA issue for cells below the quad max.
// ============================================================================
__global__ __launch_bounds__(128, 8) void gather_kernel(float* __restrict__ out)
{
    __shared__ int2  s_rec[GCELLS * STAGE];
    __shared__ int   s_cnt[GCELLS];
    __shared__ float t[C_CH * (GCELLS + 1)];

    const int tid  = threadIdx.x;
    const int warp = tid >> 5;
    const int lane = tid & 31;
    const int b    = blockIdx.x >> 9;
    const int yx0  = (blockIdx.x & 511) * GCELLS;
    const int cell0 = (b << 14) + yx0;
    const float4* ctx4 = (const float4*)g_ctx;

    if (tid < GCELLS) {
        int c = g_cnt[cell0 + tid];
        g_cnt[cell0 + tid] = 0;
        s_cnt[tid] = (c > CAP) ? CAP : c;
    }
#pragma unroll
    for (int r = 0; r < GCELLS * STAGE / 128; r++) {
        int i  = tid + 128 * r;
        int cl = i >> 5, slot = i & 31;
        s_rec[i] = g_bin[(cell0 + cl) * CAP + slot];
    }
    __syncthreads();

#pragma unroll
    for (int q = 0; q < 2; q++) {
        const int clb = warp * 8 + q * 4;          // quad base cell
        int cs[4];
        const int2* rec[4];
#pragma unroll
        for (int j = 0; j < 4; j++) {
            int cnt = s_cnt[clb + j];
            cs[j]  = (cnt < STAGE) ? cnt : STAGE;
            rec[j] = &s_rec[(clb + j) * STAGE];
        }
        int maxc = cs[0];
#pragma unroll
        for (int j = 1; j < 4; j++) maxc = (cs[j] > maxc) ? cs[j] : maxc;

        float4 acc[4];
#pragma unroll
        for (int j = 0; j < 4; j++) acc[j] = make_float4(0.f, 0.f, 0.f, 0.f);

        for (int base = 0; base < maxc; base += 2) {
#pragma unroll
            for (int j = 0; j < 4; j++) {
                if (base < cs[j]) {                          // warp-uniform guard
                    int2 r0 = rec[j][base];                  // LDS broadcast
                    int2 r1 = rec[j][(base + 1 < cs[j]) ? base + 1 : base];
                    float d0 = __int_as_float(r0.y);
                    float d1 = (base + 1 < cs[j]) ? __int_as_float(r1.y) : 0.f;
                    if (lane < 20) {
                        float4 c0 = __ldg(&ctx4[r0.x * 20 + lane]);
                        float4 c1 = __ldg(&ctx4[r1.x * 20 + lane]);
                        acc[j].x += d0 * c0.x + d1 * c1.x;
                        acc[j].y += d0 * c0.y + d1 * c1.y;
                        acc[j].z += d0 * c0.z + d1 * c1.z;
                        acc[j].w += d0 * c0.w + d1 * c1.w;
                    }
                }
            }
        }
        // rare overflow tails (cnt > STAGE)
#pragma unroll
        for (int j = 0; j < 4; j++) {
            int cnt = s_cnt[clb + j];
            for (int pt = STAGE; pt < cnt; pt++) {
                int2 rr = __ldg(&g_bin[(cell0 + clb + j) * CAP + pt]);
                float d0 = __int_as_float(rr.y);
                if (lane < 20) {
                    float4 cv = __ldg(&ctx4[rr.x * 20 + lane]);
                    acc[j].x += d0 * cv.x; acc[j].y += d0 * cv.y;
                    acc[j].z += d0 * cv.z; acc[j].w += d0 * cv.w;
                }
            }
        }
        if (lane < 20) {
            int c = lane * 4;
#pragma unroll
            for (int j = 0; j < 4; j++) {
                int cl = clb + j;
                t[(c + 0) * (GCELLS + 1) + cl] = acc[j].x;
                t[(c + 1) * (GCELLS + 1) + cl] = acc[j].y;
                t[(c + 2) * (GCELLS + 1) + cl] = acc[j].z;
                t[(c + 3) * (GCELLS + 1) + cl] = acc[j].w;
            }
        }
    }
    __syncthreads();

    float* dst = out + ((size_t)b * C_CH) * (128 * 128) + yx0;
#pragma unroll
    for (int i = tid; i < C_CH * GCELLS; i += 128) {
        int c = i >> 5;
        int j = i & 31;
        dst[(size_t)c * (128 * 128) + j] = t[c * (GCELLS + 1) + j];
    }
}

// ============================================================================
extern "C" void kernel_launch(void* const* d_in, const int* in_sizes, int n_in,
                              void* d_out, int out_size)
{
    const float* img  = (const float*)d_in[0];
    const float* wd   = (const float*)d_in[4];
    const float* bd   = (const float*)d_in[5];
    const int*   geom = (const int*)d_in[6];
    float* out = (float*)d_out;

    gemm_fused_kernel<<<NPIX / 64, 384>>>(img, wd, bd, geom);
    gather_kernel<<<2048, 128>>>(out);
}